// round 16
// baseline (speedup 1.0000x reference)
#include <cuda_runtime.h>
#include <cuda_fp16.h>
#include <mma.h>
#include <cstdint>

using namespace nvcuda;

// ---------------------------------------------------------------------------
// Problem constants
// ---------------------------------------------------------------------------
#define M_TOK   4096
#define K_IN    4096
#define N_OUT   11008
#define GROUPSZ 128

// GEMM tiling: 4 warps, warp tile 64x64, 2 CTAs/SM, 3-stage ring
#define BM      128
#define BN      128
#define BK      64
#define NITER   (K_IN / BK)        // 64
#define NTHREADS 128               // 4 warps, warp grid 2(M) x 2(N)
#define NSTAGE  3

#define A_LD    72                 // 64 + 8 pad (halves); 144B row stride
#define B_LDK   72                 // B is [n][k]: 64 + 8 pad (halves)
#define C_LD    68                 // 64 + 4 pad (floats), epilogue staging

#define A_STAGE_BYTES (BM * A_LD * 2)      // 18432
#define B_STAGE_BYTES (BN * B_LDK * 2)     // 18432
#define STAGE_BYTES   (A_STAGE_BYTES + B_STAGE_BYTES)   // 36864
#define SMEM_DYN      (NSTAGE * STAGE_BYTES)            // 110592 (x2 CTAs = 221KB)

// fp16 x scratch (no allocations allowed).
// K-PERMUTED within each 8-group: physical pos p holds original k = 8t+pi(p),
// pi = (0,4,1,5,2,6,3,7). The same permutation falls out of the B nibble-pair
// extraction, so the contraction is invariant.
__device__ __half g_Xh[(size_t)M_TOK * K_IN];

// ---------------------------------------------------------------------------
// Kernel 0: convert x f32 -> f16 with per-8-group k interleave:
// out halves = (k0,k4, k1,k5, k2,k6, k3,k7)  — free via float2half2 pairing.
// ---------------------------------------------------------------------------
__global__ void convert_x_kernel(const float* __restrict__ x)
{
    size_t i = ((size_t)blockIdx.x * blockDim.x + threadIdx.x) * 8;
    if (i >= (size_t)M_TOK * K_IN) return;
    float4 lo = *(const float4*)(x + i);
    float4 hi = *(const float4*)(x + i + 4);
    __half2 h0 = __floats2half2_rn(lo.x, hi.x);
    __half2 h1 = __floats2half2_rn(lo.y, hi.y);
    __half2 h2 = __floats2half2_rn(lo.z, hi.z);
    __half2 h3 = __floats2half2_rn(lo.w, hi.w);
    uint4 v = make_uint4(*(uint32_t*)&h0, *(uint32_t*)&h1,
                         *(uint32_t*)&h2, *(uint32_t*)&h3);
    *(uint4*)(g_Xh + i) = v;
}

// ---------------------------------------------------------------------------
// helpers
// ---------------------------------------------------------------------------
__device__ __forceinline__ uint32_t smem_u32(const void* p) {
    uint32_t a;
    asm("{ .reg .u64 t; cvta.to.shared.u64 t, %1; cvt.u32.u64 %0, t; }"
        : "=r"(a) : "l"(p));
    return a;
}
__device__ __forceinline__ void cp_async16(uint32_t saddr, const void* gaddr) {
    asm volatile("cp.async.ca.shared.global [%0], [%1], 16;\n"
                 :: "r"(saddr), "l"(gaddr));
}
#define CP_COMMIT() asm volatile("cp.async.commit_group;\n" ::: "memory")
#define CP_WAIT2()  asm volatile("cp.async.wait_group 2;\n" ::: "memory")
#define BAR_SYNC(id, cnt) \
    asm volatile("bar.sync %0, %1;" :: "r"(id), "r"(cnt) : "memory")
#define BAR_ARRIVE(id, cnt) \
    asm volatile("bar.arrive %0, %1;" :: "r"(id), "r"(cnt) : "memory")

// ---------------------------------------------------------------------------
// Fused 4-bit dequant + HMMA GEMM:  C[M,N] = X[M,K] * dequant(Q)[K,N] + bias
//
// qweight: [K/8, N] int32, nibbles pack K; qzeros: [G, N/8] nibbles pack N;
// scales: [G, N] f32 (fp16 values).
//
// B SMEM is [n][k] (wmma col_major B). Dequant uses the nibble-PAIR trick:
//   t = (w >> 4r) & 0x000F000F | 0x64006400   (one SHF + one LOP3)
// yields fp16x2 (1024+q_r, 1024+q_{r+4}) — physical k slots 2r,2r+1 under
// the global per-8-group permutation pi=(0,4,1,5,2,6,3,7) that convert_x
// also applies to A. Then (t - (1024+z))*s, bit-exact vs the fp16 reference.
// One qweight word -> 4 half2 -> one STS.128. ~2x fewer int-ALU ops than
// the per-nibble path. Col-to-thread mapping (tid&15)+16c keeps STS.128
// and LDSM phases bank-conflict-free (144B stride = 4 banks/lane).
//
// Pipeline = R15: 3-stage ring, produce ks+2, commit/iter + wait_group(2),
// arrive/sync split barrier, 2 CTAs/SM.
// ---------------------------------------------------------------------------
__global__ void __launch_bounds__(NTHREADS, 2)
gemm_q4_kernel(const int* __restrict__ qweight,
               const int* __restrict__ qzeros,
               const float* __restrict__ scales,
               const float* __restrict__ bias,
               float* __restrict__ out)
{
    extern __shared__ __align__(16) char smem[];
    const uint32_t sbase = smem_u32(smem);

    const int tid  = threadIdx.x;
    const int warp = tid >> 5;
    const int lane = tid & 31;
    const int bm   = blockIdx.x * BM;   // M fastest: A + qweight stay L2-resident
    const int bn   = blockIdx.y * BN;

    // warp tile: 64x64.  warp grid 2(M) x 2(N)
    const int wm = (warp >> 1) * 64;
    const int wn = (warp & 1) * 64;

    const __half* Xb = g_Xh + (size_t)bm * K_IN;

    // ---- B dequant mapping: 8 cols {colbase+16c}, 1 kp row per thread ----
    const int colbase = tid & 15;            // adjacent lanes -> adjacent cols
    const int kp0     = tid >> 4;            // 0..7
    const int zsh     = (colbase & 7) * 4;   // qzeros nibble shift (const per thread)

    wmma::fragment<wmma::accumulator, 16, 16, 16, float> acc[4][4];
    #pragma unroll
    for (int i = 0; i < 4; i++)
        #pragma unroll
        for (int j = 0; j < 4; j++)
            wmma::fill_fragment(acc[i][j], 0.0f);

    uint32_t br[8];           // qweight words: col colbase+16c, row kp0
    __half2  hz[8];           // (1024+z) broadcast per col
    __half2  hs[8];           // scale broadcast per col

    auto ldg_b = [&](int ks) {
        const int* qw = qweight + (size_t)(ks * 8 + kp0) * N_OUT + bn + colbase;
        #pragma unroll
        for (int c = 0; c < 8; c++)
            br[c] = (uint32_t)qw[16 * c];
    };
    auto ldg_consts = [&](int g) {
        const uint32_t* qz = (const uint32_t*)qzeros + (size_t)g * (N_OUT / 8)
                           + ((bn + colbase) >> 3);
        const float* sp = scales + (size_t)g * N_OUT + bn + colbase;
        #pragma unroll
        for (int c = 0; c < 8; c++) {
            uint32_t zw = qz[2 * c];                // 16 cols = 2 words apart
            uint32_t z  = ((zw >> zsh) & 15u) + 1u + 0x6400u;
            uint32_t p  = z | (z << 16);
            hz[c] = *(__half2*)&p;
            hs[c] = __half2half2(__float2half_rn(sp[16 * c]));
        }
    };
    auto issue_a = [&](int ks, uint32_t abase) {
        const int k0 = ks * BK;
        #pragma unroll
        for (int i = 0; i < 8; i++) {
            int c = tid + NTHREADS * i;
            int row = c >> 3, cc = c & 7;
            cp_async16(abase + (uint32_t)(row * A_LD + cc * 8) * 2,
                       Xb + (size_t)row * K_IN + k0 + cc * 8);
        }
    };
    auto store_b = [&](uint32_t bbyte) {
        #pragma unroll
        for (int c = 0; c < 8; c++) {
            uint32_t w = br[c];
            uint32_t t0 = (w         & 0x000F000Fu) | 0x64006400u;
            uint32_t t1 = ((w >> 4)  & 0x000F000Fu) | 0x64006400u;
            uint32_t t2 = ((w >> 8)  & 0x000F000Fu) | 0x64006400u;
            uint32_t t3 = ((w >> 12) & 0x000F000Fu) | 0x64006400u;
            __half2 h0 = __hmul2(__hsub2(*(__half2*)&t0, hz[c]), hs[c]);
            __half2 h1 = __hmul2(__hsub2(*(__half2*)&t1, hz[c]), hs[c]);
            __half2 h2 = __hmul2(__hsub2(*(__half2*)&t2, hz[c]), hs[c]);
            __half2 h3 = __hmul2(__hsub2(*(__half2*)&t3, hz[c]), hs[c]);
            uint4 v = make_uint4(*(uint32_t*)&h0, *(uint32_t*)&h1,
                                 *(uint32_t*)&h2, *(uint32_t*)&h3);
            // [n][k] layout: col (colbase+16c), physical k slots kp0*8..+7
            *(uint4*)(smem + bbyte
                      + (uint32_t)(colbase + 16 * c) * (B_LDK * 2)
                      + (uint32_t)kp0 * 16) = v;
        }
    };

    // ---- prologue: stages 0,1 fully staged; regs/consts ready for stage 2 ----
    ldg_consts(0);                 // group of stages 0,1
    ldg_b(0);
    issue_a(0, sbase + 0 * STAGE_BYTES);
    CP_COMMIT();
    issue_a(1, sbase + 1 * STAGE_BYTES);
    CP_COMMIT();
    store_b(0 * STAGE_BYTES + A_STAGE_BYTES);
    ldg_b(1);
    store_b(1 * STAGE_BYTES + A_STAGE_BYTES);
    ldg_consts(1);                 // group of stages 2,3
    ldg_b(2);
    __syncthreads();

    for (int ks = 0; ks < NITER; ks++) {
        const int buf  = ks % NSTAGE;
        const int nbuf = (ks + 2) % NSTAGE;
        const bool produce = (ks + 2 < NITER);

        if (produce && ks > 0)
            BAR_SYNC(1, 2 * NTHREADS);

        if (produce)
            issue_a(ks + 2, sbase + nbuf * STAGE_BYTES);
        CP_COMMIT();                          // commit every iter (may be empty)
        if (produce)
            store_b((uint32_t)(nbuf * STAGE_BYTES + A_STAGE_BYTES));
        if (ks + 3 < NITER) {
            if (ks & 1)
                ldg_consts((ks + 3) >> 1);    // group boundary ahead
            ldg_b(ks + 3);
        }

        CP_WAIT2();                           // group ks committed 2 iters ago

        // ---- compute stage ks ----
        const __half* As = (const __half*)(smem + buf * STAGE_BYTES);
        const __half* Bs = (const __half*)(smem + buf * STAGE_BYTES + A_STAGE_BYTES);
        #pragma unroll
        for (int kk = 0; kk < BK; kk += 16) {
            wmma::fragment<wmma::matrix_a, 16, 16, 16, __half, wmma::row_major> af[4];
            #pragma unroll
            for (int i = 0; i < 4; i++)
                wmma::load_matrix_sync(af[i], As + (wm + i * 16) * A_LD + kk, A_LD);
            #pragma unroll
            for (int j = 0; j < 4; j++) {
                wmma::fragment<wmma::matrix_b, 16, 16, 16, __half, wmma::col_major> bf;
                wmma::load_matrix_sync(bf, Bs + (size_t)(wn + j * 16) * B_LDK + kk, B_LDK);
                #pragma unroll
                for (int i = 0; i < 4; i++)
                    wmma::mma_sync(acc[i][j], af[i], bf, acc[i][j]);
            }
        }

        BAR_ARRIVE(1, 2 * NTHREADS);          // readers of stage-ks done (LDSM issued)
    }

    __syncthreads();   // full barrier before smem reuse by the epilogue

    // ---- epilogue: stage fp32 per warp (16x64 chunks), add bias, write ----
    float* fbuf = (float*)(smem + STAGE_BYTES) + warp * 16 * C_LD;
    const float* brow = bias + bn + wn;
    #pragma unroll
    for (int i = 0; i < 4; i++) {
        #pragma unroll
        for (int j = 0; j < 4; j++)
            wmma::store_matrix_sync(fbuf + j * 16, acc[i][j], C_LD, wmma::mem_row_major);
        __syncwarp();
        #pragma unroll
        for (int ii = 0; ii < 8; ii++) {
            int idx4 = lane + 32 * ii;          // 256 float4 = 16x64
            int row  = idx4 >> 4;
            int col  = (idx4 & 15) * 4;
            float4 v = *(float4*)(fbuf + row * C_LD + col);
            float4 b4 = *(const float4*)(brow + col);
            v.x += b4.x; v.y += b4.y; v.z += b4.z; v.w += b4.w;
            *(float4*)(out + (size_t)(bm + wm + i * 16 + row) * N_OUT + bn + wn + col) = v;
        }
        __syncwarp();
    }
}

// ---------------------------------------------------------------------------
// Launch.  Inputs: x(f32), qweight(i32), qzeros(i32), scales(f32), g_idx(i32),
//                  bias(f32).  Output f32 [M_TOK, N_OUT].
// ---------------------------------------------------------------------------
extern "C" void kernel_launch(void* const* d_in, const int* in_sizes, int n_in,
                              void* d_out, int out_size)
{
    const float* x       = (const float*)d_in[0];
    const int*   qweight = (const int*)d_in[1];
    const int*   qzeros  = (const int*)d_in[2];
    const float* scales  = (const float*)d_in[3];
    const float* bias    = (const float*)d_in[5];
    float* out = (float*)d_out;

    {
        size_t n8 = (size_t)M_TOK * K_IN / 8;
        convert_x_kernel<<<(unsigned)((n8 + 255) / 256), 256>>>(x);
    }
    {
        cudaFuncSetAttribute(gemm_q4_kernel,
                             cudaFuncAttributeMaxDynamicSharedMemorySize,
                             SMEM_DYN);
        dim3 grid(M_TOK / BM, N_OUT / BN);   // (32, 86), M fastest
        gemm_q4_kernel<<<grid, NTHREADS, SMEM_DYN>>>(qweight, qzeros, scales, bias, out);
    }
}